// round 1
// baseline (speedup 1.0000x reference)
#include <cuda_runtime.h>
#include <math.h>

#define BATCH 8
#define CIN   512
#define CK    256
#define CV    256
#define CO    512
#define NPIX  4096
#define EPSBN 1e-5f

// ---------------- scratch (no allocs allowed; __device__ globals) ----------------
__device__ float g_qk[BATCH * CK * NPIX];                    // 33.5 M floats
__device__ float g_sim[(size_t)BATCH * NPIX * NPIX];         // 134.2 M floats (536 MB)
__device__ float g_ctx[(size_t)BATCH * NPIX * CV];           // ctx transposed: [b][n][cv]
__device__ float g_mean[CK];
__device__ float g_rstd[CK];

// ============================================================================
// K1: fused qk/value 1x1-conv GEMM.
//   y[b, m, n] = sum_k Wcat[m,k] * x[b,k,n] + bias[m]
//   m in [0,256) -> g_qk ; m in [256,512) -> value output section
// Tiles 128x128x8, 256 threads, 8x8 per thread.
// ============================================================================
__global__ __launch_bounds__(256, 2)
void qkv_gemm(const float* __restrict__ x, const float* __restrict__ Wk,
              const float* __restrict__ bk, const float* __restrict__ Wv,
              const float* __restrict__ bv, float* __restrict__ value_out) {
    const int b  = blockIdx.z;
    const int mT = blockIdx.y * 128;
    const int nT = blockIdx.x * 128;
    const int tid = threadIdx.x;

    __shared__ float As[8][132];
    __shared__ float Bs[8][132];

    const int tx = tid & 15, ty = tid >> 4;

    // A-tile load mapping: 128 rows x 8 cols, transpose store
    const int a_row = tid >> 1;           // 0..127
    const int a_col = (tid & 1) * 4;      // 0 or 4
    const int mg = mT + a_row;
    const float* Arow = (mg < CK) ? (Wk + (size_t)mg * CIN)
                                  : (Wv + (size_t)(mg - CK) * CIN);
    // B-tile load mapping: 8 rows x 128 cols, direct store
    const int b_row = tid >> 5;           // 0..7
    const int b_col = (tid & 31) * 4;     // 0..124
    const float* Bbase = x + (size_t)b * CIN * NPIX + nT + b_col;

    float acc[8][8];
#pragma unroll
    for (int i = 0; i < 8; i++)
#pragma unroll
        for (int j = 0; j < 8; j++) acc[i][j] = 0.f;

    for (int kt = 0; kt < CIN; kt += 8) {
        float4 av = *(const float4*)(Arow + kt + a_col);
        float4 bvv = *(const float4*)(Bbase + (size_t)(kt + b_row) * NPIX);
        As[a_col + 0][a_row] = av.x;
        As[a_col + 1][a_row] = av.y;
        As[a_col + 2][a_row] = av.z;
        As[a_col + 3][a_row] = av.w;
        *(float4*)&Bs[b_row][b_col] = bvv;
        __syncthreads();
#pragma unroll
        for (int kk = 0; kk < 8; kk++) {
            float a[8], bb[8];
            *(float4*)(a)      = *(const float4*)&As[kk][ty * 4];
            *(float4*)(a + 4)  = *(const float4*)&As[kk][64 + ty * 4];
            *(float4*)(bb)     = *(const float4*)&Bs[kk][tx * 4];
            *(float4*)(bb + 4) = *(const float4*)&Bs[kk][64 + tx * 4];
#pragma unroll
            for (int i = 0; i < 8; i++)
#pragma unroll
                for (int j = 0; j < 8; j++)
                    acc[i][j] = fmaf(a[i], bb[j], acc[i][j]);
        }
        __syncthreads();
    }

#pragma unroll
    for (int i = 0; i < 8; i++) {
        const int r = (i < 4) ? (ty * 4 + i) : (64 + ty * 4 + i - 4);
        const int m = mT + r;
        float bias;
        float* dst;
        if (m < CK) { bias = bk[m];      dst = g_qk     + ((size_t)(b * CK + m)) * NPIX + nT; }
        else        { bias = bv[m - CK]; dst = value_out + ((size_t)(b * CV + (m - CK))) * NPIX + nT; }
        float4 v0 = make_float4(acc[i][0] + bias, acc[i][1] + bias, acc[i][2] + bias, acc[i][3] + bias);
        float4 v1 = make_float4(acc[i][4] + bias, acc[i][5] + bias, acc[i][6] + bias, acc[i][7] + bias);
        *(float4*)(dst + tx * 4)      = v0;
        *(float4*)(dst + 64 + tx * 4) = v1;
    }
}

// ============================================================================
// K2: BatchNorm training stats per channel (mean, biased var -> rstd)
// ============================================================================
__global__ void bn_stats() {
    const int o = blockIdx.x;
    const int tid = threadIdx.x;
    float s1 = 0.f, s2 = 0.f;
    for (int idx = tid; idx < BATCH * NPIX; idx += 256) {
        const int b = idx >> 12;
        const int n = idx & (NPIX - 1);
        float v = g_qk[((size_t)(b * CK + o)) * NPIX + n];
        s1 += v;
        s2 += v * v;
    }
#pragma unroll
    for (int off = 16; off > 0; off >>= 1) {
        s1 += __shfl_xor_sync(0xffffffffu, s1, off);
        s2 += __shfl_xor_sync(0xffffffffu, s2, off);
    }
    __shared__ float sh1[8], sh2[8];
    const int wid = tid >> 5, lane = tid & 31;
    if (lane == 0) { sh1[wid] = s1; sh2[wid] = s2; }
    __syncthreads();
    if (tid == 0) {
        float t1 = 0.f, t2 = 0.f;
#pragma unroll
        for (int w = 0; w < 8; w++) { t1 += sh1[w]; t2 += sh2[w]; }
        const float inv_n = 1.f / (float)(BATCH * NPIX);
        const float mean = t1 * inv_n;
        const float var = t2 * inv_n - mean * mean;
        g_mean[o] = mean;
        g_rstd[o] = rsqrtf(var + EPSBN);
    }
}

// ============================================================================
// K3: feat = relu((qk - mean) * rstd * gamma + beta); written to both feat
// output sections. float4 per thread.
// ============================================================================
__global__ void feat_kernel(const float* __restrict__ gamma, const float* __restrict__ beta,
                            float* __restrict__ f1, float* __restrict__ f2) {
    const size_t idx4 = (size_t)blockIdx.x * 256 + threadIdx.x;   // float4 index
    const int ch = (int)((idx4 >> 10) & 255);                      // 1024 float4 per row of 4096
    float4 q = ((const float4*)g_qk)[idx4];
    const float m = g_mean[ch];
    const float s = g_rstd[ch] * gamma[ch];
    const float bt = beta[ch];
    float4 r;
    r.x = fmaxf(0.f, (q.x - m) * s + bt);
    r.y = fmaxf(0.f, (q.y - m) * s + bt);
    r.z = fmaxf(0.f, (q.z - m) * s + bt);
    r.w = fmaxf(0.f, (q.w - m) * s + bt);
    ((float4*)f1)[idx4] = r;
    ((float4*)f2)[idx4] = r;
}

// ============================================================================
// K4: sim[b,i,j] = scale * sum_c F[b,c,i] * F[b,c,j]   (F = feat, k-major loads)
// ============================================================================
__global__ __launch_bounds__(256, 2)
void sim_gemm(const float* __restrict__ feat) {
    const int b  = blockIdx.z;
    const int iT = blockIdx.y * 128;
    const int jT = blockIdx.x * 128;
    const float* F = feat + (size_t)b * CK * NPIX;
    const int tid = threadIdx.x;

    __shared__ float As[8][132];
    __shared__ float Bs[8][132];

    const int tx = tid & 15, ty = tid >> 4;
    const int l_row = tid >> 5;            // k 0..7
    const int l_col = (tid & 31) * 4;      // 0..124

    float acc[8][8];
#pragma unroll
    for (int i = 0; i < 8; i++)
#pragma unroll
        for (int j = 0; j < 8; j++) acc[i][j] = 0.f;

    for (int kt = 0; kt < CK; kt += 8) {
        const float* Frow = F + (size_t)(kt + l_row) * NPIX;
        float4 av = *(const float4*)(Frow + iT + l_col);
        float4 bvv = *(const float4*)(Frow + jT + l_col);
        *(float4*)&As[l_row][l_col] = av;
        *(float4*)&Bs[l_row][l_col] = bvv;
        __syncthreads();
#pragma unroll
        for (int kk = 0; kk < 8; kk++) {
            float a[8], bb[8];
            *(float4*)(a)      = *(const float4*)&As[kk][ty * 4];
            *(float4*)(a + 4)  = *(const float4*)&As[kk][64 + ty * 4];
            *(float4*)(bb)     = *(const float4*)&Bs[kk][tx * 4];
            *(float4*)(bb + 4) = *(const float4*)&Bs[kk][64 + tx * 4];
#pragma unroll
            for (int i = 0; i < 8; i++)
#pragma unroll
                for (int j = 0; j < 8; j++)
                    acc[i][j] = fmaf(a[i], bb[j], acc[i][j]);
        }
        __syncthreads();
    }

    const float scale = 0.0625f;   // 256^-0.5
#pragma unroll
    for (int i = 0; i < 8; i++) {
        const int r = (i < 4) ? (ty * 4 + i) : (64 + ty * 4 + i - 4);
        float* dst = g_sim + ((size_t)b * NPIX + (iT + r)) * NPIX + jT;
        float4 v0 = make_float4(acc[i][0] * scale, acc[i][1] * scale, acc[i][2] * scale, acc[i][3] * scale);
        float4 v1 = make_float4(acc[i][4] * scale, acc[i][5] * scale, acc[i][6] * scale, acc[i][7] * scale);
        *(float4*)(dst + tx * 4)      = v0;
        *(float4*)(dst + 64 + tx * 4) = v1;
    }
}

// ============================================================================
// K5: row softmax over g_sim, in place. One block per row of 4096.
// ============================================================================
__global__ void softmax_kernel() {
    const size_t row = blockIdx.x;
    float* p = g_sim + row * NPIX;
    const int tid = threadIdx.x;

    float4 v[4];
    float mx = -3.4e38f;
#pragma unroll
    for (int u = 0; u < 4; u++) {
        v[u] = ((const float4*)p)[tid + u * 256];
        mx = fmaxf(mx, fmaxf(fmaxf(v[u].x, v[u].y), fmaxf(v[u].z, v[u].w)));
    }
#pragma unroll
    for (int off = 16; off > 0; off >>= 1)
        mx = fmaxf(mx, __shfl_xor_sync(0xffffffffu, mx, off));

    __shared__ float shm[8], shs[8];
    const int wid = tid >> 5, lane = tid & 31;
    if (lane == 0) shm[wid] = mx;
    __syncthreads();
    mx = shm[0];
#pragma unroll
    for (int w = 1; w < 8; w++) mx = fmaxf(mx, shm[w]);

    float s = 0.f;
#pragma unroll
    for (int u = 0; u < 4; u++) {
        v[u].x = __expf(v[u].x - mx); s += v[u].x;
        v[u].y = __expf(v[u].y - mx); s += v[u].y;
        v[u].z = __expf(v[u].z - mx); s += v[u].z;
        v[u].w = __expf(v[u].w - mx); s += v[u].w;
    }
#pragma unroll
    for (int off = 16; off > 0; off >>= 1)
        s += __shfl_xor_sync(0xffffffffu, s, off);
    if (lane == 0) shs[wid] = s;
    __syncthreads();
    float tot = 0.f;
#pragma unroll
    for (int w = 0; w < 8; w++) tot += shs[w];
    const float inv = 1.f / tot;

#pragma unroll
    for (int u = 0; u < 4; u++) {
        v[u].x *= inv; v[u].y *= inv; v[u].z *= inv; v[u].w *= inv;
        ((float4*)p)[tid + u * 256] = v[u];
    }
}

// ============================================================================
// K6: ctxT[b,i,cv] = sum_j P[b,i,j] * V[b,cv,j]    (K = 4096)
// Both tiles transpose-stored to k-major smem.
// ============================================================================
__global__ __launch_bounds__(256, 2)
void ctx_gemm(const float* __restrict__ value) {
    const int b   = blockIdx.z;
    const int iT  = blockIdx.y * 128;
    const int cvT = blockIdx.x * 128;
    const float* P = g_sim + (size_t)b * NPIX * NPIX;
    const float* V = value + (size_t)b * CV * NPIX;
    const int tid = threadIdx.x;

    __shared__ float As[8][132];
    __shared__ float Bs[8][132];

    const int tx = tid & 15, ty = tid >> 4;
    const int a_row = tid >> 1;        // 0..127
    const int a_col = (tid & 1) * 4;   // 0 or 4

    const float* Prow = P + (size_t)(iT + a_row) * NPIX + a_col;
    const float* Vrow = V + (size_t)(cvT + a_row) * NPIX + a_col;

    float acc[8][8];
#pragma unroll
    for (int i = 0; i < 8; i++)
#pragma unroll
        for (int j = 0; j < 8; j++) acc[i][j] = 0.f;

    for (int jt = 0; jt < NPIX; jt += 8) {
        float4 av = *(const float4*)(Prow + jt);
        float4 bvv = *(const float4*)(Vrow + jt);
        As[a_col + 0][a_row] = av.x;
        As[a_col + 1][a_row] = av.y;
        As[a_col + 2][a_row] = av.z;
        As[a_col + 3][a_row] = av.w;
        Bs[a_col + 0][a_row] = bvv.x;
        Bs[a_col + 1][a_row] = bvv.y;
        Bs[a_col + 2][a_row] = bvv.z;
        Bs[a_col + 3][a_row] = bvv.w;
        __syncthreads();
#pragma unroll
        for (int kk = 0; kk < 8; kk++) {
            float a[8], bb[8];
            *(float4*)(a)      = *(const float4*)&As[kk][ty * 4];
            *(float4*)(a + 4)  = *(const float4*)&As[kk][64 + ty * 4];
            *(float4*)(bb)     = *(const float4*)&Bs[kk][tx * 4];
            *(float4*)(bb + 4) = *(const float4*)&Bs[kk][64 + tx * 4];
#pragma unroll
            for (int i = 0; i < 8; i++)
#pragma unroll
                for (int j = 0; j < 8; j++)
                    acc[i][j] = fmaf(a[i], bb[j], acc[i][j]);
        }
        __syncthreads();
    }

#pragma unroll
    for (int i = 0; i < 8; i++) {
        const int r = (i < 4) ? (ty * 4 + i) : (64 + ty * 4 + i - 4);
        float* dst = g_ctx + ((size_t)b * NPIX + (iT + r)) * CV + cvT;
        float4 v0 = make_float4(acc[i][0], acc[i][1], acc[i][2], acc[i][3]);
        float4 v1 = make_float4(acc[i][4], acc[i][5], acc[i][6], acc[i][7]);
        *(float4*)(dst + tx * 4)      = v0;
        *(float4*)(dst + 64 + tx * 4) = v1;
    }
}

// ============================================================================
// K7: out[b,o,n] = sum_cv Ww[o,cv] * ctxT[b,n,cv] + bw[o]
// ============================================================================
__global__ __launch_bounds__(256, 2)
void out_gemm(const float* __restrict__ Ww, const float* __restrict__ bw,
              float* __restrict__ out) {
    const int b  = blockIdx.z;
    const int oT = blockIdx.y * 128;
    const int nT = blockIdx.x * 128;
    const int tid = threadIdx.x;

    __shared__ float As[8][132];
    __shared__ float Bs[8][132];

    const int tx = tid & 15, ty = tid >> 4;
    const int a_row = tid >> 1;
    const int a_col = (tid & 1) * 4;

    const float* Arow = Ww + (size_t)(oT + a_row) * CV + a_col;
    const float* Brow = g_ctx + ((size_t)b * NPIX + (nT + a_row)) * CV + a_col;

    float acc[8][8];
#pragma unroll
    for (int i = 0; i < 8; i++)
#pragma unroll
        for (int j = 0; j < 8; j++) acc[i][j] = 0.f;

    for (int kt = 0; kt < CV; kt += 8) {
        float4 av = *(const float4*)(Arow + kt);
        float4 bvv = *(const float4*)(Brow + kt);
        As[a_col + 0][a_row] = av.x;
        As[a_col + 1][a_row] = av.y;
        As[a_col + 2][a_row] = av.z;
        As[a_col + 3][a_row] = av.w;
        Bs[a_col + 0][a_row] = bvv.x;
        Bs[a_col + 1][a_row] = bvv.y;
        Bs[a_col + 2][a_row] = bvv.z;
        Bs[a_col + 3][a_row] = bvv.w;
        __syncthreads();
#pragma unroll
        for (int kk = 0; kk < 8; kk++) {
            float a[8], bb[8];
            *(float4*)(a)      = *(const float4*)&As[kk][ty * 4];
            *(float4*)(a + 4)  = *(const float4*)&As[kk][64 + ty * 4];
            *(float4*)(bb)     = *(const float4*)&Bs[kk][tx * 4];
            *(float4*)(bb + 4) = *(const float4*)&Bs[kk][64 + tx * 4];
#pragma unroll
            for (int i = 0; i < 8; i++)
#pragma unroll
                for (int j = 0; j < 8; j++)
                    acc[i][j] = fmaf(a[i], bb[j], acc[i][j]);
        }
        __syncthreads();
    }

#pragma unroll
    for (int i = 0; i < 8; i++) {
        const int r = (i < 4) ? (ty * 4 + i) : (64 + ty * 4 + i - 4);
        const int o = oT + r;
        const float bias = bw[o];
        float* dst = out + ((size_t)(b * CO + o)) * NPIX + nT;
        float4 v0 = make_float4(acc[i][0] + bias, acc[i][1] + bias, acc[i][2] + bias, acc[i][3] + bias);
        float4 v1 = make_float4(acc[i][4] + bias, acc[i][5] + bias, acc[i][6] + bias, acc[i][7] + bias);
        *(float4*)(dst + tx * 4)      = v0;
        *(float4*)(dst + 64 + tx * 4) = v1;
    }
}

// ============================================================================
// launch
// ============================================================================
extern "C" void kernel_launch(void* const* d_in, const int* in_sizes, int n_in,
                              void* d_out, int out_size) {
    const float* x     = (const float*)d_in[0];
    const float* Wk    = (const float*)d_in[1];
    const float* bk    = (const float*)d_in[2];
    const float* gamma = (const float*)d_in[3];
    const float* beta  = (const float*)d_in[4];
    const float* Wv    = (const float*)d_in[5];
    const float* bv    = (const float*)d_in[6];
    const float* Ww    = (const float*)d_in[7];
    const float* bw    = (const float*)d_in[8];

    float* out   = (float*)d_out;
    float* feat1 = out + (size_t)BATCH * CO * NPIX;        // 16777216
    float* feat2 = feat1 + (size_t)BATCH * CK * NPIX;      // +8388608
    float* valO  = feat2 + (size_t)BATCH * CK * NPIX;      // +8388608

    qkv_gemm<<<dim3(32, 4, BATCH), 256>>>(x, Wk, bk, Wv, bv, valO);
    bn_stats<<<CK, 256>>>();
    feat_kernel<<<(BATCH * CK * NPIX / 4) / 256, 256>>>(gamma, beta, feat1, feat2);
    sim_gemm<<<dim3(32, 32, BATCH), 256>>>(feat1);
    softmax_kernel<<<BATCH * NPIX, 256>>>();
    ctx_gemm<<<dim3(2, 32, BATCH), 256>>>(valO);
    out_gemm<<<dim3(32, 4, BATCH), 256>>>(Ww, bw, out);
}

// round 7
// speedup vs baseline: 2.9940x; 2.9940x over previous
#include <cuda_runtime.h>
#include <cuda_bf16.h>
#include <math.h>
#include <cstdint>

#define BATCH 8
#define CIN   512
#define CK    256
#define CV    256
#define CO    512
#define NPIX  4096
#define EPSBN 1e-5f

// ---------------- scratch (__device__ globals; no allocs allowed) ----------------
__device__ float g_qk[(size_t)BATCH * CK * NPIX];
__device__ float g_sim[(size_t)BATCH * NPIX * NPIX];          // fp32 logits staging
__device__ float g_ctx[(size_t)BATCH * NPIX * CV];            // [b][n][cv]
__device__ float g_mean[CK];
__device__ float g_rstd[CK];
// bf16 split operands
__device__ __align__(16) __nv_bfloat16 g_fhi[(size_t)BATCH * NPIX * CK];   // featT [b][n][c]
__device__ __align__(16) __nv_bfloat16 g_flo[(size_t)BATCH * NPIX * CK];
__device__ __align__(16) __nv_bfloat16 g_vhi[(size_t)BATCH * CV * NPIX];   // value [b][cv][j]
__device__ __align__(16) __nv_bfloat16 g_vlo[(size_t)BATCH * CV * NPIX];
__device__ __align__(16) __nv_bfloat16 g_phi[(size_t)BATCH * NPIX * NPIX]; // P [b][i][j]
__device__ __align__(16) __nv_bfloat16 g_plo[(size_t)BATCH * NPIX * NPIX];

// ======================= arch-neutral PTX helpers =======================
__device__ __forceinline__ uint32_t smem_to_u32(const void* smem_ptr) {
    uint32_t addr;
    asm("{ .reg .u64 tmp; cvta.to.shared.u64 tmp, %1; cvt.u32.u64 %0, tmp; }"
        : "=r"(addr) : "l"(smem_ptr));
    return addr;
}
#define SWZ_(off) ((off) ^ (((off) >> 3) & 0x70))

#define CP_ASYNC16(SADDR, GPTR) \
    asm volatile("cp.async.cg.shared.global [%0], [%1], 16;" \
        :: "r"(SADDR), "l"(GPTR) : "memory")
#define CP_ASYNC_COMMIT() asm volatile("cp.async.commit_group;" ::: "memory")

#define LDSM_X4(R0, R1, R2, R3, ADDR) \
    asm volatile("ldmatrix.sync.aligned.m8n8.x4.shared.b16 {%0,%1,%2,%3}, [%4];" \
        : "=r"(R0), "=r"(R1), "=r"(R2), "=r"(R3) : "r"(ADDR))

#define MMA_BF16(C, A, B) \
    asm volatile("mma.sync.aligned.m16n8k16.row.col.f32.bf16.bf16.f32 " \
        "{%0,%1,%2,%3}, {%4,%5,%6,%7}, {%8,%9}, {%0,%1,%2,%3};" \
        : "+f"((C)[0]), "+f"((C)[1]), "+f"((C)[2]), "+f"((C)[3]) \
        : "r"((A)[0]), "r"((A)[1]), "r"((A)[2]), "r"((A)[3]), \
          "r"((B)[0]), "r"((B)[1]))

// smem: 2 stages x (Ah 16K | Al 16K | Bh 16K | Bl 16K) = 128 KB dynamic
#define STAGE_BYTES 65536
#define OFF_AH 0
#define OFF_AL 16384
#define OFF_BH 32768
#define OFF_BL 49152
#define SMEM_DYN (2 * STAGE_BYTES)

extern __shared__ char smem_dyn[];

// ============================================================================
// 128x128 tile, K in chunks of 64 bf16, 3xBF16-split GEMM body.
// A rows: m (128), k-major, stride lda. B rows: n (128), k-major, stride ldb.
// C written fp32 to cOut (row-major, stride ldc), scaled.
// 8 warps: wm = wid&1 (2 x 64 rows), wn = wid>>1 (4 x 32 cols).
// ============================================================================
__device__ __forceinline__ void gemm128x128(
    const __nv_bfloat16* __restrict__ aHi, const __nv_bfloat16* __restrict__ aLo, int lda,
    const __nv_bfloat16* __restrict__ bHi, const __nv_bfloat16* __restrict__ bLo, int ldb,
    float* __restrict__ cOut, int ldc, int nchunk, float scale)
{
    const uint32_t smem = smem_to_u32(smem_dyn);
    const int tid  = threadIdx.x;
    const int lane = tid & 31;
    const int wid  = tid >> 5;
    const int wm   = wid & 1;
    const int wn   = wid >> 1;

    // ldmatrix lane geometry
    const int lrA   = wm * 64 + (lane & 15);
    const int lrB   = wn * 32 + (lane & 15);
    const int khalf = (lane >> 4) * 16;          // byte offset for k 8..15 half

    float c[4][4][4];
#pragma unroll
    for (int mi = 0; mi < 4; ++mi)
#pragma unroll
        for (int ni = 0; ni < 4; ++ni)
#pragma unroll
            for (int q = 0; q < 4; ++q) c[mi][ni][q] = 0.f;

    // cp.async chunk loader: 1024 16B-chunks per 16KB tile, 4 per thread
    auto load_chunk = [&](int stageIdx, int ck) {
        const uint32_t st = smem + stageIdx * STAGE_BYTES;
        const int kc = ck * 64;
#pragma unroll
        for (int it = 0; it < 4; ++it) {
            const int cc  = it * 256 + tid;
            const int row = cc >> 3;
            const int off = cc & 7;
            const uint32_t sw = SWZ_((uint32_t)(row * 128 + off * 16));
            const size_t ea = (size_t)row * lda + kc + off * 8;
            const size_t eb = (size_t)row * ldb + kc + off * 8;
            CP_ASYNC16(st + OFF_AH + sw, aHi + ea);
            CP_ASYNC16(st + OFF_AL + sw, aLo + ea);
            CP_ASYNC16(st + OFF_BH + sw, bHi + eb);
            CP_ASYNC16(st + OFF_BL + sw, bLo + eb);
        }
        CP_ASYNC_COMMIT();
    };

    load_chunk(0, 0);

    for (int ck = 0; ck < nchunk; ++ck) {
        const int s = ck & 1;
        if (ck + 1 < nchunk) {
            load_chunk(s ^ 1, ck + 1);
            asm volatile("cp.async.wait_group 1;" ::: "memory");
        } else {
            asm volatile("cp.async.wait_group 0;" ::: "memory");
        }
        __syncthreads();

        const uint32_t st = smem + s * STAGE_BYTES;
#pragma unroll
        for (int k16 = 0; k16 < 4; ++k16) {
            uint32_t ah[4][4], al[4][4], bh[4][2], bl[4][2];
#pragma unroll
            for (int mi = 0; mi < 4; ++mi) {
                const uint32_t off = (uint32_t)((lrA + mi * 16) * 128 + k16 * 32 + khalf);
                const uint32_t sw = SWZ_(off);
                LDSM_X4(ah[mi][0], ah[mi][1], ah[mi][2], ah[mi][3], st + OFF_AH + sw);
                LDSM_X4(al[mi][0], al[mi][1], al[mi][2], al[mi][3], st + OFF_AL + sw);
            }
#pragma unroll
            for (int p = 0; p < 2; ++p) {
                const uint32_t off = (uint32_t)((lrB + p * 16) * 128 + k16 * 32 + khalf);
                const uint32_t sw = SWZ_(off);
                LDSM_X4(bh[2 * p][0], bh[2 * p + 1][0], bh[2 * p][1], bh[2 * p + 1][1],
                        st + OFF_BH + sw);
                LDSM_X4(bl[2 * p][0], bl[2 * p + 1][0], bl[2 * p][1], bl[2 * p + 1][1],
                        st + OFF_BL + sw);
            }
#pragma unroll
            for (int mi = 0; mi < 4; ++mi)
#pragma unroll
                for (int ni = 0; ni < 4; ++ni) {
                    MMA_BF16(c[mi][ni], ah[mi], bh[ni]);
                    MMA_BF16(c[mi][ni], ah[mi], bl[ni]);
                    MMA_BF16(c[mi][ni], al[mi], bh[ni]);
                }
        }
        __syncthreads();
    }

    // epilogue: fp32 stores (float2 per half-fragment)
    const int g   = lane >> 2;
    const int tig = lane & 3;
#pragma unroll
    for (int mi = 0; mi < 4; ++mi) {
        const int r0 = wm * 64 + mi * 16 + g;
#pragma unroll
        for (int ni = 0; ni < 4; ++ni) {
            const int cc = wn * 32 + ni * 8 + tig * 2;
            float2 v0 = make_float2(c[mi][ni][0] * scale, c[mi][ni][1] * scale);
            float2 v1 = make_float2(c[mi][ni][2] * scale, c[mi][ni][3] * scale);
            *(float2*)(cOut + (size_t)r0 * ldc + cc)       = v0;
            *(float2*)(cOut + (size_t)(r0 + 8) * ldc + cc) = v1;
        }
    }
}

// ============================================================================
// K4: sim[b, i, j] = scale * feat_i . feat_j   (K = 256)
// ============================================================================
__global__ __launch_bounds__(256, 1)
void sim_mma() {
    const int b  = blockIdx.z;
    const int iT = blockIdx.y * 128;
    const int jT = blockIdx.x * 128;
    const __nv_bfloat16* aH = g_fhi + ((size_t)(b << 12) + iT) * CK;
    const __nv_bfloat16* aL = g_flo + ((size_t)(b << 12) + iT) * CK;
    const __nv_bfloat16* bH = g_fhi + ((size_t)(b << 12) + jT) * CK;
    const __nv_bfloat16* bL = g_flo + ((size_t)(b << 12) + jT) * CK;
    float* cO = g_sim + ((size_t)(b << 12) + iT) * NPIX + jT;
    gemm128x128(aH, aL, CK, bH, bL, CK, cO, NPIX, CK / 64, 0.0625f);
}

// ============================================================================
// K6: ctx[b, i, cv] = P[b,i,:] . V[b,cv,:]   (K = 4096)
// ============================================================================
__global__ __launch_bounds__(256, 1)
void ctx_mma() {
    const int b  = blockIdx.z;
    const int iT = blockIdx.y * 128;
    const int vT = blockIdx.x * 128;
    const __nv_bfloat16* aH = g_phi + ((size_t)(b << 12) + iT) * NPIX;
    const __nv_bfloat16* aL = g_plo + ((size_t)(b << 12) + iT) * NPIX;
    const __nv_bfloat16* bH = g_vhi + ((size_t)(b * CV) + vT) * NPIX;
    const __nv_bfloat16* bL = g_vlo + ((size_t)(b * CV) + vT) * NPIX;
    float* cO = g_ctx + ((size_t)(b << 12) + iT) * CV + vT;
    gemm128x128(aH, aL, NPIX, bH, bL, NPIX, cO, CV, NPIX / 64, 1.0f);
}

// ============================================================================
// K1: fused qk/value 1x1-conv GEMM (FFMA).
// ============================================================================
__global__ __launch_bounds__(256, 2)
void qkv_gemm(const float* __restrict__ x, const float* __restrict__ Wk,
              const float* __restrict__ bk, const float* __restrict__ Wv,
              const float* __restrict__ bv, float* __restrict__ value_out) {
    const int b  = blockIdx.z;
    const int mT = blockIdx.y * 128;
    const int nT = blockIdx.x * 128;
    const int tid = threadIdx.x;

    __shared__ float As[8][132];
    __shared__ float Bs[8][132];

    const int tx = tid & 15, ty = tid >> 4;
    const int a_row = tid >> 1;
    const int a_col = (tid & 1) * 4;
    const int mg = mT + a_row;
    const float* Arow = (mg < CK) ? (Wk + (size_t)mg * CIN)
                                  : (Wv + (size_t)(mg - CK) * CIN);
    const int b_row = tid >> 5;
    const int b_col = (tid & 31) * 4;
    const float* Bbase = x + (size_t)b * CIN * NPIX + nT + b_col;

    float acc[8][8];
#pragma unroll
    for (int i = 0; i < 8; i++)
#pragma unroll
        for (int j = 0; j < 8; j++) acc[i][j] = 0.f;

    for (int kt = 0; kt < CIN; kt += 8) {
        float4 av = *(const float4*)(Arow + kt + a_col);
        float4 bvv = *(const float4*)(Bbase + (size_t)(kt + b_row) * NPIX);
        As[a_col + 0][a_row] = av.x;
        As[a_col + 1][a_row] = av.y;
        As[a_col + 2][a_row] = av.z;
        As[a_col + 3][a_row] = av.w;
        *(float4*)&Bs[b_row][b_col] = bvv;
        __syncthreads();
#pragma unroll
        for (int kk = 0; kk < 8; kk++) {
            float a[8], bb[8];
            *(float4*)(a)      = *(const float4*)&As[kk][ty * 4];
            *(float4*)(a + 4)  = *(const float4*)&As[kk][64 + ty * 4];
            *(float4*)(bb)     = *(const float4*)&Bs[kk][tx * 4];
            *(float4*)(bb + 4) = *(const float4*)&Bs[kk][64 + tx * 4];
#pragma unroll
            for (int i = 0; i < 8; i++)
#pragma unroll
                for (int j = 0; j < 8; j++)
                    acc[i][j] = fmaf(a[i], bb[j], acc[i][j]);
        }
        __syncthreads();
    }

#pragma unroll
    for (int i = 0; i < 8; i++) {
        const int r = (i < 4) ? (ty * 4 + i) : (64 + ty * 4 + i - 4);
        const int m = mT + r;
        float bias;
        float* dst;
        if (m < CK) { bias = bk[m];      dst = g_qk      + ((size_t)(b * CK + m)) * NPIX + nT; }
        else        { bias = bv[m - CK]; dst = value_out + ((size_t)(b * CV + (m - CK))) * NPIX + nT; }
        float4 v0 = make_float4(acc[i][0] + bias, acc[i][1] + bias, acc[i][2] + bias, acc[i][3] + bias);
        float4 v1 = make_float4(acc[i][4] + bias, acc[i][5] + bias, acc[i][6] + bias, acc[i][7] + bias);
        *(float4*)(dst + tx * 4)      = v0;
        *(float4*)(dst + 64 + tx * 4) = v1;
    }
}

// ============================================================================
// K2: BN stats
// ============================================================================
__global__ void bn_stats() {
    const int o = blockIdx.x;
    const int tid = threadIdx.x;
    float s1 = 0.f, s2 = 0.f;
    for (int idx = tid; idx < BATCH * NPIX; idx += 256) {
        const int b = idx >> 12;
        const int n = idx & (NPIX - 1);
        float v = g_qk[((size_t)(b * CK + o)) * NPIX + n];
        s1 += v;
        s2 += v * v;
    }
#pragma unroll
    for (int off = 16; off > 0; off >>= 1) {
        s1 += __shfl_xor_sync(0xffffffffu, s1, off);
        s2 += __shfl_xor_sync(0xffffffffu, s2, off);
    }
    __shared__ float sh1[8], sh2[8];
    const int wid = tid >> 5, lane = tid & 31;
    if (lane == 0) { sh1[wid] = s1; sh2[wid] = s2; }
    __syncthreads();
    if (tid == 0) {
        float t1 = 0.f, t2 = 0.f;
#pragma unroll
        for (int w = 0; w < 8; w++) { t1 += sh1[w]; t2 += sh2[w]; }
        const float inv_n = 1.f / (float)(BATCH * NPIX);
        const float mean = t1 * inv_n;
        const float var = t2 * inv_n - mean * mean;
        g_mean[o] = mean;
        g_rstd[o] = rsqrtf(var + EPSBN);
    }
}

// ============================================================================
// K3: feat fp32 outputs (both copies)
// ============================================================================
__global__ void feat_kernel(const float* __restrict__ gamma, const float* __restrict__ beta,
                            float* __restrict__ f1, float* __restrict__ f2) {
    const size_t idx4 = (size_t)blockIdx.x * 256 + threadIdx.x;
    const int ch = (int)((idx4 >> 10) & 255);
    float4 q = ((const float4*)g_qk)[idx4];
    const float m = g_mean[ch];
    const float s = g_rstd[ch] * gamma[ch];
    const float bt = beta[ch];
    float4 r;
    r.x = fmaxf(0.f, (q.x - m) * s + bt);
    r.y = fmaxf(0.f, (q.y - m) * s + bt);
    r.z = fmaxf(0.f, (q.z - m) * s + bt);
    r.w = fmaxf(0.f, (q.w - m) * s + bt);
    ((float4*)f1)[idx4] = r;
    ((float4*)f2)[idx4] = r;
}

// ============================================================================
// K3b: featT: BN+ReLU on g_qk, transposed to [b][n][c], bf16 hi/lo split
// ============================================================================
__global__ void featT_kernel(const float* __restrict__ gamma, const float* __restrict__ beta) {
    __shared__ float tile[32][33];
    const int b  = blockIdx.z;
    const int n0 = blockIdx.x * 32;
    const int c0 = blockIdx.y * 32;
    const int tx = threadIdx.x, ty = threadIdx.y;   // 32 x 8
#pragma unroll
    for (int k = 0; k < 4; ++k) {
        const int c = c0 + ty + k * 8;
        float v = g_qk[(((size_t)(b * CK + c)) << 12) + n0 + tx];
        const float s = g_rstd[c] * gamma[c];
        v = fmaxf(0.f, (v - g_mean[c]) * s + beta[c]);
        tile[ty + k * 8][tx] = v;
    }
    __syncthreads();
#pragma unroll
    for (int k = 0; k < 4; ++k) {
        const int n = n0 + ty + k * 8;
        const float v = tile[tx][ty + k * 8];
        __nv_bfloat16 h = __float2bfloat16_rn(v);
        __nv_bfloat16 l = __float2bfloat16_rn(v - __bfloat162float(h));
        const size_t o = (((size_t)(b << 12)) + n) * CK + c0 + tx;
        g_fhi[o] = h;
        g_flo[o] = l;
    }
}

// ============================================================================
// K3c: value bf16 hi/lo split (same [b][cv][j] layout)
// ============================================================================
__global__ void vcvt_kernel(const float* __restrict__ val) {
    const size_t i4 = (size_t)blockIdx.x * 256 + threadIdx.x;
    float4 v = ((const float4*)val)[i4];
    __nv_bfloat16 h0 = __float2bfloat16_rn(v.x), h1 = __float2bfloat16_rn(v.y);
    __nv_bfloat16 h2 = __float2bfloat16_rn(v.z), h3 = __float2bfloat16_rn(v.w);
    __nv_bfloat16 l0 = __float2bfloat16_rn(v.x - __bfloat162float(h0));
    __nv_bfloat16 l1 = __float2bfloat16_rn(v.y - __bfloat162float(h1));
    __nv_bfloat16 l2 = __float2bfloat16_rn(v.z - __bfloat162float(h2));
    __nv_bfloat16 l3 = __float2bfloat16_rn(v.w - __bfloat162float(h3));
    __nv_bfloat162* ph = (__nv_bfloat162*)g_vhi;
    __nv_bfloat162* pl = (__nv_bfloat162*)g_vlo;
    ph[i4 * 2 + 0] = __halves2bfloat162(h0, h1);
    ph[i4 * 2 + 1] = __halves2bfloat162(h2, h3);
    pl[i4 * 2 + 0] = __halves2bfloat162(l0, l1);
    pl[i4 * 2 + 1] = __halves2bfloat162(l2, l3);
}

// ============================================================================
// K5: softmax: g_sim fp32 -> P hi/lo bf16
// ============================================================================
__global__ void softmax_kernel() {
    const size_t row = blockIdx.x;
    const float* p = g_sim + row * NPIX;
    __nv_bfloat162* ph = (__nv_bfloat162*)(g_phi + row * NPIX);
    __nv_bfloat162* pl = (__nv_bfloat162*)(g_plo + row * NPIX);
    const int tid = threadIdx.x;

    float4 v[4];
    float mx = -3.4e38f;
#pragma unroll
    for (int u = 0; u < 4; u++) {
        v[u] = ((const float4*)p)[tid + u * 256];
        mx = fmaxf(mx, fmaxf(fmaxf(v[u].x, v[u].y), fmaxf(v[u].z, v[u].w)));
    }
#pragma unroll
    for (int off = 16; off > 0; off >>= 1)
        mx = fmaxf(mx, __shfl_xor_sync(0xffffffffu, mx, off));

    __shared__ float shm[8], shs[8];
    const int wid = tid >> 5, lane = tid & 31;
    if (lane == 0) shm[wid] = mx;
    __syncthreads();
    mx = shm[0];
#pragma unroll
    for (int w = 1; w < 8; w++) mx = fmaxf(mx, shm[w]);

    float s = 0.f;
#pragma unroll
    for (int u = 0; u < 4; u++) {
        v[u].x = __expf(v[u].x - mx); s += v[u].x;
        v[u].y = __expf(v[u].y - mx); s += v[u].y;
        v[u].z = __expf(v[u].z - mx); s += v[u].z;
        v[u].w = __expf(v[u].w - mx); s += v[u].w;
    }
#pragma unroll
    for (int off = 16; off > 0; off >>= 1)
        s += __shfl_xor_sync(0xffffffffu, s, off);
    if (lane == 0) shs[wid] = s;
    __syncthreads();
    float tot = 0.f;
#pragma unroll
    for (int w = 0; w < 8; w++) tot += shs[w];
    const float inv = 1.f / tot;

#pragma unroll
    for (int u = 0; u < 4; u++) {
        const float a0 = v[u].x * inv, a1 = v[u].y * inv, a2 = v[u].z * inv, a3 = v[u].w * inv;
        __nv_bfloat16 h0 = __float2bfloat16_rn(a0), h1 = __float2bfloat16_rn(a1);
        __nv_bfloat16 h2 = __float2bfloat16_rn(a2), h3 = __float2bfloat16_rn(a3);
        __nv_bfloat16 l0 = __float2bfloat16_rn(a0 - __bfloat162float(h0));
        __nv_bfloat16 l1 = __float2bfloat16_rn(a1 - __bfloat162float(h1));
        __nv_bfloat16 l2 = __float2bfloat16_rn(a2 - __bfloat162float(h2));
        __nv_bfloat16 l3 = __float2bfloat16_rn(a3 - __bfloat162float(h3));
        const int f = tid + u * 256;
        ph[f * 2 + 0] = __halves2bfloat162(h0, h1);
        ph[f * 2 + 1] = __halves2bfloat162(h2, h3);
        pl[f * 2 + 0] = __halves2bfloat162(l0, l1);
        pl[f * 2 + 1] = __halves2bfloat162(l2, l3);
    }
}

// ============================================================================
// K7: out GEMM (FFMA)
// ============================================================================
__global__ __launch_bounds__(256, 2)
void out_gemm(const float* __restrict__ Ww, const float* __restrict__ bw,
              float* __restrict__ out) {
    const int b  = blockIdx.z;
    const int oT = blockIdx.y * 128;
    const int nT = blockIdx.x * 128;
    const int tid = threadIdx.x;

    __shared__ float As[8][132];
    __shared__ float Bs[8][132];

    const int tx = tid & 15, ty = tid >> 4;
    const int a_row = tid >> 1;
    const int a_col = (tid & 1) * 4;

    const float* Arow = Ww + (size_t)(oT + a_row) * CV + a_col;
    const float* Brow = g_ctx + ((size_t)b * NPIX + (nT + a_row)) * CV + a_col;

    float acc[8][8];
#pragma unroll
    for (int i = 0; i < 8; i++)
#pragma unroll
        for (int j = 0; j < 8; j++) acc[i][j] = 0.f;

    for (int kt = 0; kt < CV; kt += 8) {
        float4 av = *(const float4*)(Arow + kt);
        float4 bvv = *(const float4*)(Brow + kt);
        As[a_col + 0][a_row] = av.x;
        As[a_col + 1][a_row] = av.y;
        As[a_col + 2][a_row] = av.z;
        As[a_col + 3][a_row] = av.w;
        Bs[a_col + 0][a_row] = bvv.x;
        Bs[a_col + 1][a_row] = bvv.y;
        Bs[a_col + 2][a_row] = bvv.z;
        Bs[a_col + 3][a_row] = bvv.w;
        __syncthreads();
#pragma unroll
        for (int kk = 0; kk < 8; kk++) {
            float a[8], bb[8];
            *(float4*)(a)      = *(const float4*)&As[kk][ty * 4];
            *(float4*)(a + 4)  = *(const float4*)&As[kk][64 + ty * 4];
            *(float4*)(bb)     = *(const float4*)&Bs[kk][tx * 4];
            *(float4*)(bb + 4) = *(const float4*)&Bs[kk][64 + tx * 4];
#pragma unroll
            for (int i = 0; i < 8; i++)
#pragma unroll
                for (int j = 0; j < 8; j++)
                    acc[i][j] = fmaf(a[i], bb[j], acc[i][j]);
        }
        __syncthreads();
    }

#pragma unroll
    for (int i = 0; i < 8; i++) {
        const int r = (i < 4) ? (ty * 4 + i) : (64 + ty * 4 + i - 4);
        const int o = oT + r;
        const float bias = bw[o];
        float* dst = out + ((size_t)(b * CO + o)) * NPIX + nT;
        float4 v0 = make_float4(acc[i][0] + bias, acc[i][1] + bias, acc[i][2] + bias, acc[i][3] + bias);
        float4 v1 = make_float4(acc[i][4] + bias, acc[i][5] + bias, acc[i][6] + bias, acc[i][7] + bias);
        *(float4*)(dst + tx * 4)      = v0;
        *(float4*)(dst + 64 + tx * 4) = v1;
    }
}

// ============================================================================
// launch
// ============================================================================
extern "C" void kernel_launch(void* const* d_in, const int* in_sizes, int n_in,
                              void* d_out, int out_size) {
    const float* x     = (const float*)d_in[0];
    const float* Wk    = (const float*)d_in[1];
    const float* bk    = (const float*)d_in[2];
    const float* gamma = (const float*)d_in[3];
    const float* beta  = (const float*)d_in[4];
    const float* Wv    = (const float*)d_in[5];
    const float* bv    = (const float*)d_in[6];
    const float* Ww    = (const float*)d_in[7];
    const float* bw    = (const float*)d_in[8];

    float* out   = (float*)d_out;
    float* feat1 = out + (size_t)BATCH * CO * NPIX;
    float* feat2 = feat1 + (size_t)BATCH * CK * NPIX;
    float* valO  = feat2 + (size_t)BATCH * CK * NPIX;

    cudaFuncSetAttribute(sim_mma, cudaFuncAttributeMaxDynamicSharedMemorySize, SMEM_DYN);
    cudaFuncSetAttribute(ctx_mma, cudaFuncAttributeMaxDynamicSharedMemorySize, SMEM_DYN);

    qkv_gemm<<<dim3(32, 4, BATCH), 256>>>(x, Wk, bk, Wv, bv, valO);
    bn_stats<<<CK, 256>>>();
    feat_kernel<<<(BATCH * CK * NPIX / 4) / 256, 256>>>(gamma, beta, feat1, feat2);
    featT_kernel<<<dim3(NPIX / 32, CK / 32, BATCH), dim3(32, 8)>>>(gamma, beta);
    vcvt_kernel<<<(BATCH * CV * NPIX / 4) / 256, 256>>>(valO);
    sim_mma<<<dim3(NPIX / 128, NPIX / 128, BATCH), 256, SMEM_DYN>>>();
    softmax_kernel<<<BATCH * NPIX, 256>>>();
    ctx_mma<<<dim3(CV / 128, NPIX / 128, BATCH), 256, SMEM_DYN>>>();
    out_gemm<<<dim3(32, 4, BATCH), 256>>>(Ww, bw, out);
}